// round 15
// baseline (speedup 1.0000x reference)
#include <cuda_runtime.h>
#include <cuda_fp16.h>
#include <cstdint>

// Problem constants
#define N_NODES 100000
#define IN_F    256
#define HID     128
#define OUTF    64

// Scratch (device globals — no allocation allowed).
__device__ uint4 g_h0h[(size_t)N_NODES * HID / 8];   // x@W1+b1        (fp16)
__device__ uint4 g_hh [(size_t)N_NODES * HID / 8];   // relu(spmm(h0)) (fp16)
__device__ uint4 g_z0h[(size_t)N_NODES * OUTF / 8];  // h@W2+b2        (fp16)
__device__ float g_z [(size_t)N_NODES * OUTF];       // spmm(z0)       fp32
__device__ int   g_rp[N_NODES + 1];                  // CSR row pointers
// Pre-converted fp16 weights, chunk-major transposed [kc][n][64k].
__device__ uint4 g_w1[IN_F * HID / 8];
__device__ uint4 g_w2[HID * OUTF / 8];

// ===========================================================================
// Build CSR row_ptr from the sorted rows array.
// ===========================================================================
__global__ void build_rowptr_kernel(const int* __restrict__ rows, int nnz) {
    int e = blockIdx.x * blockDim.x + threadIdx.x;
    if (e >= nnz) return;
    int r = rows[e];
    int rprev = (e == 0) ? -1 : rows[e - 1];
    for (int rr = rprev + 1; rr <= r; ++rr) g_rp[rr] = e;
    if (e == nnz - 1) {
        for (int rr = r + 1; rr <= N_NODES; ++rr) g_rp[rr] = nnz;
    }
}

// ===========================================================================
// Pre-convert W[K,BN] fp32 -> fp16, chunk-major transposed:
//   dst[(kc*BN + n)*64 + kl], kc = k/64, kl = k%64
// ===========================================================================
__global__ void conv_w_kernel(const float* __restrict__ W,
                              __half* __restrict__ Wh, int K, int BN) {
    int idx = blockIdx.x * blockDim.x + threadIdx.x;
    if (idx >= K * BN) return;
    int k = idx / BN, n = idx % BN;
    Wh[((size_t)(k >> 6) * BN + n) * 64 + (k & 63)] =
        __float2half(W[(size_t)k * BN + n]);
}

// ===========================================================================
// mma.sync m16n8k16 fp16 -> fp32 accumulate, ldmatrix, cp.async
// ===========================================================================
__device__ __forceinline__ void mma_fp16(float* c, const uint32_t* a,
                                         uint32_t b0, uint32_t b1) {
    asm volatile(
        "mma.sync.aligned.m16n8k16.row.col.f32.f16.f16.f32 "
        "{%0,%1,%2,%3}, {%4,%5,%6,%7}, {%8,%9}, {%0,%1,%2,%3};"
        : "+f"(c[0]), "+f"(c[1]), "+f"(c[2]), "+f"(c[3])
        : "r"(a[0]), "r"(a[1]), "r"(a[2]), "r"(a[3]), "r"(b0), "r"(b1));
}
__device__ __forceinline__ void ldsm_x4(uint32_t* r, uint32_t addr) {
    asm volatile("ldmatrix.sync.aligned.m8n8.x4.shared.b16 {%0,%1,%2,%3}, [%4];"
                 : "=r"(r[0]), "=r"(r[1]), "=r"(r[2]), "=r"(r[3]) : "r"(addr));
}
__device__ __forceinline__ void ldsm_x2(uint32_t* r, uint32_t addr) {
    asm volatile("ldmatrix.sync.aligned.m8n8.x2.shared.b16 {%0,%1}, [%2];"
                 : "=r"(r[0]), "=r"(r[1]) : "r"(addr));
}
__device__ __forceinline__ void cp_async16(uint32_t dst, const void* src) {
    size_t g = __cvta_generic_to_global(src);
    asm volatile("cp.async.cg.shared.global [%0], [%1], 16;"
                 :: "r"(dst), "l"(g) : "memory");
}
__device__ __forceinline__ void cp_commit() {
    asm volatile("cp.async.commit_group;" ::: "memory");
}
__device__ __forceinline__ void cp_wait0() {
    asm volatile("cp.async.wait_group 0;" ::: "memory");
}

// ===========================================================================
// Single-pass fp16 GEMM + bias: C[M,BN] = A[M,K] @ W[K,BN] + b (fp16 out)
// CTA: 64 x BN, BK=64 chunks. 8 warps 2(m) x 4(n); warp tile 32 x BN/4.
// A_FP16=false: A fp32, register-prefetch + in-kernel convert (gemm1).
// A_FP16=true : A already fp16, pure cp.async copy (gemm2, zero convert).
// W pre-converted fp16, cp.async per chunk. Smem stride 72 halves.
// ===========================================================================
template <int K_TOTAL, int BN, bool A_FP16>
__global__ __launch_bounds__(256) void mma_gemm_fp16(
    const void* __restrict__ Ap, const __half* __restrict__ Wg,
    const float* __restrict__ bias, __half* __restrict__ C, int M)
{
    constexpr int BM = 64, BK = 64, LDSW = 72;
    constexpr int CHUNKS = K_TOTAL / BK;
    constexpr int WN = BN / 4;
    constexpr int NT = WN / 8;
    constexpr int MT = 2;

    extern __shared__ __half sm[];
    __half* Ah = sm;                    // [BM][LDSW]
    __half* Bh = sm + BM * LDSW;        // [BN][LDSW]

    const int tid = threadIdx.x;
    const int wid = tid >> 5;
    const int lane = tid & 31;
    const int wm = wid >> 2;
    const int wn = wid & 3;
    const int lr = lane >> 2;
    const int lc = lane & 3;
    const int r0 = blockIdx.x * BM;

    const int m4    = lane >> 3;
    const int arow  = (lane & 7) + (m4 & 1) * 8;
    const int akoff = (m4 >> 1) * 8;
    const int brow  = lane & 7;
    const int bkoff = ((lane >> 3) & 1) * 8;

    const uint32_t smem_u32 = (uint32_t)__cvta_generic_to_shared(sm);
    const uint32_t AhB = smem_u32 + ((wm * 32 + arow) * LDSW + akoff) * 2;
    const uint32_t AhU = smem_u32;
    const uint32_t BhU = smem_u32 + BM * LDSW * 2;
    const uint32_t BhB = BhU + ((wn * WN + brow) * LDSW + bkoff) * 2;

    float acc[MT][NT][4];
#pragma unroll
    for (int i = 0; i < MT; ++i)
#pragma unroll
        for (int j = 0; j < NT; ++j)
#pragma unroll
            for (int q = 0; q < 4; ++q) acc[i][j][q] = 0.f;

    // ---- W chunk copy via cp.async: BN rows of 128B (8 x 16B) ----
    auto copy_w = [&](int kc) {
        const __half* gw = Wg + (size_t)kc * BN * 64;
#pragma unroll
        for (int it = 0; it < (BN * 8) / 256; ++it) {
            int idx = tid + it * 256;
            int row = idx >> 3;
            int j = idx & 7;
            cp_async16(BhU + row * (LDSW * 2) + j * 16, gw + row * 64 + j * 8);
        }
    };
    // ---- A chunk copy (fp16 path): BM rows of 128B (8 x 16B) ----
    auto copy_a16 = [&](int kc) {
        const __half* ga = (const __half*)Ap;
#pragma unroll
        for (int it = 0; it < (BM * 8) / 256; ++it) {
            int idx = tid + it * 256;
            int row = idx >> 3;
            int j = idx & 7;
            int gr = r0 + row; if (gr >= M) gr = M - 1;   // clamp (rows unused)
            cp_async16(AhU + row * (LDSW * 2) + j * 16,
                       ga + (size_t)gr * K_TOTAL + kc * BK + j * 8);
        }
    };
    // ---- A chunk stage (fp32 path): 4 float4 per thread ----
    float4 aStage[4];
    auto load_stage = [&](int kc) {
        const float* ga = (const float*)Ap;
#pragma unroll
        for (int it = 0; it < 4; ++it) {
            int idx = tid + it * 256;
            int row = idx >> 4;
            int j4 = (idx & 15) * 4;
            aStage[it] = make_float4(0.f, 0.f, 0.f, 0.f);
            if (r0 + row < M)
                aStage[it] = *(const float4*)(ga + (size_t)(r0 + row) * K_TOTAL +
                                              kc * BK + j4);
        }
    };

    if (A_FP16) { copy_a16(0); copy_w(0); cp_commit(); }
    else        { load_stage(0); copy_w(0); cp_commit(); }

    for (int kc = 0; kc < CHUNKS; ++kc) {
        if (!A_FP16) {
            // convert staged A -> smem fp16
#pragma unroll
            for (int it = 0; it < 4; ++it) {
                int idx = tid + it * 256;
                int row = idx >> 4;
                int j4 = (idx & 15) * 4;
                float4 v = aStage[it];
                int o = row * LDSW + j4;
                *(__half2*)(Ah + o)     = __floats2half2_rn(v.x, v.y);
                *(__half2*)(Ah + o + 2) = __floats2half2_rn(v.z, v.w);
            }
            if (kc + 1 < CHUNKS) load_stage(kc + 1);  // overlaps MMA below
        }

        cp_wait0();
        __syncthreads();

        // ---- MMA: 4 k16 steps ----
#pragma unroll
        for (int ks = 0; ks < BK / 16; ++ks) {
            const int k0 = ks * 16;
            uint32_t a[MT][4];
#pragma unroll
            for (int i = 0; i < MT; ++i)
                ldsm_x4(a[i], AhB + (i * 16 * LDSW + k0) * 2);
#pragma unroll
            for (int j = 0; j < NT; ++j) {
                uint32_t b[2];
                ldsm_x2(b, BhB + (j * 8 * LDSW + k0) * 2);
#pragma unroll
                for (int i = 0; i < MT; ++i)
                    mma_fp16(acc[i][j], a[i], b[0], b[1]);
            }
        }
        if (kc + 1 < CHUNKS) {
            __syncthreads();                 // smem free for next chunk
            if (A_FP16) copy_a16(kc + 1);
            copy_w(kc + 1);
            cp_commit();
        }
    }

    // ---- epilogue: bias add + fp16 store ----
#pragma unroll
    for (int j = 0; j < NT; ++j) {
        int col = wn * WN + j * 8 + 2 * lc;
        float bb0 = __ldg(bias + col);
        float bb1 = __ldg(bias + col + 1);
#pragma unroll
        for (int i = 0; i < MT; ++i) {
            int row = r0 + wm * 32 + i * 16 + lr;
            if (row < M)
                *(__half2*)(C + (size_t)row * BN + col) =
                    __floats2half2_rn(acc[i][j][0] + bb0, acc[i][j][1] + bb1);
            if (row + 8 < M)
                *(__half2*)(C + (size_t)(row + 8) * BN + col) =
                    __floats2half2_rn(acc[i][j][2] + bb0, acc[i][j][3] + bb1);
        }
    }
}

// ===========================================================================
// CSR SpMM over fp16 features. Thread owns 8 features (one LDG.128/edge).
// 8-way edge unroll. OUT16: fp16 output (one 16B store) else fp32.
// ===========================================================================
template <int F, bool RELU, bool OUT16>
__global__ __launch_bounds__(128) void spmm_fp16_kernel(
    const int* __restrict__ cols, const float* __restrict__ vals,
    const uint4* __restrict__ dense, void* __restrict__ out)
{
    constexpr int F8 = F / 8;
    constexpr int RPB = 128 / F8;
    const int r = blockIdx.x * RPB + threadIdx.x / F8;
    if (r >= N_NODES) return;
    const int f = threadIdx.x % F8;

    int e = g_rp[r];
    const int e_end = g_rp[r + 1];

    float2 a0 = make_float2(0.f, 0.f), a1 = a0, a2 = a0, a3 = a0;

    auto accum = [&](float v, uint4 d) {
        const __half2* ph = (const __half2*)&d;
        float2 x0 = __half22float2(ph[0]);
        float2 x1 = __half22float2(ph[1]);
        float2 x2 = __half22float2(ph[2]);
        float2 x3 = __half22float2(ph[3]);
        a0.x = fmaf(v, x0.x, a0.x); a0.y = fmaf(v, x0.y, a0.y);
        a1.x = fmaf(v, x1.x, a1.x); a1.y = fmaf(v, x1.y, a1.y);
        a2.x = fmaf(v, x2.x, a2.x); a2.y = fmaf(v, x2.y, a2.y);
        a3.x = fmaf(v, x3.x, a3.x); a3.y = fmaf(v, x3.y, a3.y);
    };

    for (; e + 8 <= e_end; e += 8) {
        int   c[8];
        float v[8];
#pragma unroll
        for (int u = 0; u < 8; ++u) c[u] = __ldg(cols + e + u);
#pragma unroll
        for (int u = 0; u < 8; ++u) v[u] = __ldg(vals + e + u);
        uint4 d[8];
#pragma unroll
        for (int u = 0; u < 8; ++u) d[u] = __ldg(dense + (size_t)c[u] * F8 + f);
#pragma unroll
        for (int u = 0; u < 8; ++u) accum(v[u], d[u]);
    }
    for (; e + 4 <= e_end; e += 4) {
        int   c[4];
        float v[4];
#pragma unroll
        for (int u = 0; u < 4; ++u) c[u] = __ldg(cols + e + u);
#pragma unroll
        for (int u = 0; u < 4; ++u) v[u] = __ldg(vals + e + u);
        uint4 d[4];
#pragma unroll
        for (int u = 0; u < 4; ++u) d[u] = __ldg(dense + (size_t)c[u] * F8 + f);
#pragma unroll
        for (int u = 0; u < 4; ++u) accum(v[u], d[u]);
    }
    for (; e < e_end; ++e) {
        int c = __ldg(cols + e);
        float v = __ldg(vals + e);
        accum(v, __ldg(dense + (size_t)c * F8 + f));
    }

    if (RELU) {
        a0.x = fmaxf(a0.x, 0.f); a0.y = fmaxf(a0.y, 0.f);
        a1.x = fmaxf(a1.x, 0.f); a1.y = fmaxf(a1.y, 0.f);
        a2.x = fmaxf(a2.x, 0.f); a2.y = fmaxf(a2.y, 0.f);
        a3.x = fmaxf(a3.x, 0.f); a3.y = fmaxf(a3.y, 0.f);
    }
    if (OUT16) {
        __half2 h[4] = { __floats2half2_rn(a0.x, a0.y),
                         __floats2half2_rn(a1.x, a1.y),
                         __floats2half2_rn(a2.x, a2.y),
                         __floats2half2_rn(a3.x, a3.y) };
        *(uint4*)((__half*)out + (size_t)r * F + f * 8) = *(const uint4*)h;
    } else {
        float* po = (float*)out + (size_t)r * F + f * 8;
        *(float4*)po       = make_float4(a0.x, a0.y, a1.x, a1.y);
        *(float4*)(po + 4) = make_float4(a2.x, a2.y, a3.x, a3.y);
    }
}

// ===========================================================================
// Decode: out[q] = dot(z[src[q]], z[dst[q]]) over OUTF=64. Warp per edge.
// ===========================================================================
__global__ void decode_kernel(const int* __restrict__ ei,
                              const float* __restrict__ z,
                              float* __restrict__ out, int eq)
{
    int q = blockIdx.x * 8 + (threadIdx.x >> 5);
    if (q >= eq) return;
    int lane = threadIdx.x & 31;
    int s = __ldg(ei + q);
    int d = __ldg(ei + eq + q);
    const float* zs = z + (size_t)s * OUTF;
    const float* zd = z + (size_t)d * OUTF;
    float p = zs[lane] * zd[lane] + zs[lane + 32] * zd[lane + 32];
#pragma unroll
    for (int o = 16; o > 0; o >>= 1) p += __shfl_down_sync(0xffffffffu, p, o);
    if (lane == 0) out[q] = p;
}

// ===========================================================================
// Launch
// ===========================================================================
extern "C" void kernel_launch(void* const* d_in, const int* in_sizes, int n_in,
                              void* d_out, int out_size)
{
    const float* x        = (const float*)d_in[0];   // [N, 256]
    const int*   adj_rows = (const int*)  d_in[1];   // [NNZ] sorted
    const int*   adj_cols = (const int*)  d_in[2];   // [NNZ]
    const float* adj_vals = (const float*)d_in[3];   // [NNZ]
    const int*   edge_idx = (const int*)  d_in[4];   // [2, EQ]
    const float* W1       = (const float*)d_in[5];   // [256, 128]
    const float* b1       = (const float*)d_in[6];   // [128]
    const float* W2       = (const float*)d_in[7];   // [128, 64]
    const float* b2       = (const float*)d_in[8];   // [64]
    float* out = (float*)d_out;                      // [EQ]

    const int nnz = in_sizes[1];
    const int eq  = in_sizes[4] / 2;
    const int M   = N_NODES;

    uint4* h0h = nullptr; cudaGetSymbolAddress((void**)&h0h, g_h0h);
    uint4* hh  = nullptr; cudaGetSymbolAddress((void**)&hh,  g_hh);
    uint4* z0h = nullptr; cudaGetSymbolAddress((void**)&z0h, g_z0h);
    float* z   = nullptr; cudaGetSymbolAddress((void**)&z,   g_z);
    __half* w1 = nullptr; cudaGetSymbolAddress((void**)&w1, g_w1);
    __half* w2 = nullptr; cudaGetSymbolAddress((void**)&w2, g_w2);

    // Dynamic smem: (BM + BN) * 72 halves * 2 B
    constexpr int SMEM1 = (64 + 128) * 72 * 2;  // 27648
    constexpr int SMEM2 = (64 + 64) * 72 * 2;   // 18432
    cudaFuncSetAttribute(mma_gemm_fp16<IN_F, HID, false>,
                         cudaFuncAttributeMaxDynamicSharedMemorySize, SMEM1);
    cudaFuncSetAttribute(mma_gemm_fp16<HID, OUTF, true>,
                         cudaFuncAttributeMaxDynamicSharedMemorySize, SMEM2);

    const int gblocks = (M + 63) / 64;   // 1563

    // 0. pre-convert weights (fp16, chunk-major transposed)
    conv_w_kernel<<<(IN_F * HID + 255) / 256, 256>>>(W1, w1, IN_F, HID);
    conv_w_kernel<<<(HID * OUTF + 255) / 256, 256>>>(W2, w2, HID, OUTF);

    // 1. row pointers from sorted rows
    build_rowptr_kernel<<<(nnz + 255) / 256, 256>>>(adj_rows, nnz);

    // 2. h0 = x @ W1 + b1   (fp32 A converted in-kernel)
    mma_gemm_fp16<IN_F, HID, false><<<gblocks, 256, SMEM1>>>(
        x, w1, b1, (__half*)h0h, M);

    // 3. h = relu(spmm(h0)) -> fp16
    spmm_fp16_kernel<HID, true, true><<<(M + 7) / 8, 128>>>(
        adj_cols, adj_vals, h0h, hh);

    // 4. z0 = h @ W2 + b2   (fp16 A direct cp.async, zero convert)
    mma_gemm_fp16<HID, OUTF, true><<<gblocks, 256, SMEM2>>>(
        hh, w2, b2, (__half*)z0h, M);

    // 5. z = spmm(z0) -> fp32
    spmm_fp16_kernel<OUTF, false, false><<<(M + 15) / 16, 128>>>(
        adj_cols, adj_vals, z0h, z);

    // 6. edge dot products
    decode_kernel<<<(eq + 7) / 8, 256>>>(edge_idx, z, out, eq);
}

// round 16
// speedup vs baseline: 1.3856x; 1.3856x over previous
#include <cuda_runtime.h>
#include <cuda_fp16.h>
#include <cstdint>

// Problem constants
#define N_NODES 100000
#define IN_F    256
#define HID     128
#define OUTF    64

// Scratch (device globals — no allocation allowed).
__device__ uint4 g_h0h[(size_t)N_NODES * HID / 8];   // x@W1+b1        (fp16)
__device__ float g_h [(size_t)N_NODES * HID];        // relu(spmm(h0)) fp32
__device__ uint4 g_z0h[(size_t)N_NODES * OUTF / 8];  // h@W2+b2        (fp16)
__device__ float g_z [(size_t)N_NODES * OUTF];       // spmm(z0)       fp32
__device__ int   g_rp[N_NODES + 1];                  // CSR row pointers
// Pre-converted fp16 weights, chunk-major transposed [kc][n][64k].
__device__ uint4 g_w1[IN_F * HID / 8];
__device__ uint4 g_w2[HID * OUTF / 8];

// ===========================================================================
// Build CSR row_ptr from the sorted rows array.
// ===========================================================================
__global__ void build_rowptr_kernel(const int* __restrict__ rows, int nnz) {
    int e = blockIdx.x * blockDim.x + threadIdx.x;
    if (e >= nnz) return;
    int r = rows[e];
    int rprev = (e == 0) ? -1 : rows[e - 1];
    for (int rr = rprev + 1; rr <= r; ++rr) g_rp[rr] = e;
    if (e == nnz - 1) {
        for (int rr = r + 1; rr <= N_NODES; ++rr) g_rp[rr] = nnz;
    }
}

// ===========================================================================
// Pre-convert W[K,BN] fp32 -> fp16, chunk-major transposed:
//   dst[(kc*BN + n)*64 + kl], kc = k/64, kl = k%64
// ===========================================================================
__global__ void conv_w_kernel(const float* __restrict__ W,
                              __half* __restrict__ Wh, int K, int BN) {
    int idx = blockIdx.x * blockDim.x + threadIdx.x;
    if (idx >= K * BN) return;
    int k = idx / BN, n = idx % BN;
    Wh[((size_t)(k >> 6) * BN + n) * 64 + (k & 63)] =
        __float2half(W[(size_t)k * BN + n]);
}

// ===========================================================================
// mma.sync m16n8k16 fp16 -> fp32 accumulate, ldmatrix, cp.async
// ===========================================================================
__device__ __forceinline__ void mma_fp16(float* c, const uint32_t* a,
                                         uint32_t b0, uint32_t b1) {
    asm volatile(
        "mma.sync.aligned.m16n8k16.row.col.f32.f16.f16.f32 "
        "{%0,%1,%2,%3}, {%4,%5,%6,%7}, {%8,%9}, {%0,%1,%2,%3};"
        : "+f"(c[0]), "+f"(c[1]), "+f"(c[2]), "+f"(c[3])
        : "r"(a[0]), "r"(a[1]), "r"(a[2]), "r"(a[3]), "r"(b0), "r"(b1));
}
__device__ __forceinline__ void ldsm_x4(uint32_t* r, uint32_t addr) {
    asm volatile("ldmatrix.sync.aligned.m8n8.x4.shared.b16 {%0,%1,%2,%3}, [%4];"
                 : "=r"(r[0]), "=r"(r[1]), "=r"(r[2]), "=r"(r[3]) : "r"(addr));
}
__device__ __forceinline__ void ldsm_x2(uint32_t* r, uint32_t addr) {
    asm volatile("ldmatrix.sync.aligned.m8n8.x2.shared.b16 {%0,%1}, [%2];"
                 : "=r"(r[0]), "=r"(r[1]) : "r"(addr));
}
__device__ __forceinline__ void cp_async16(uint32_t dst, const void* src) {
    size_t g = __cvta_generic_to_global(src);
    asm volatile("cp.async.cg.shared.global [%0], [%1], 16;"
                 :: "r"(dst), "l"(g) : "memory");
}
__device__ __forceinline__ void cp_commit() {
    asm volatile("cp.async.commit_group;" ::: "memory");
}
__device__ __forceinline__ void cp_wait0() {
    asm volatile("cp.async.wait_group 0;" ::: "memory");
}

// ===========================================================================
// Single-pass fp16 GEMM + bias, double-buffered: C = A[M,K] @ W[K,BN] + b
// A fp32 (register prefetch + in-kernel fp16 convert); W pre-converted fp16
// via cp.async. CTA: 64 x BN, BK=64 chunks; 8 warps 2(m) x 4(n).
// Two smem buffers for A and W: next-chunk fill fully overlaps current MMA;
// ONE __syncthreads per chunk. fp16 output.
// ===========================================================================
template <int K_TOTAL, int BN>
__global__ __launch_bounds__(256) void mma_gemm_fp16(
    const float* __restrict__ A, const __half* __restrict__ Wg,
    const float* __restrict__ bias, __half* __restrict__ C, int M)
{
    constexpr int BM = 64, BK = 64, LDSW = 72;
    constexpr int CHUNKS = K_TOTAL / BK;
    constexpr int WN = BN / 4;
    constexpr int NT = WN / 8;
    constexpr int MT = 2;
    constexpr int ASTR = BM * LDSW;          // halves per A buffer
    constexpr int BSTR = BN * LDSW;          // halves per W buffer

    extern __shared__ __half sm[];
    __half* AhBuf = sm;                      // [2][BM][LDSW]
    // W buffers live at sm + 2*ASTR

    const int tid = threadIdx.x;
    const int wid = tid >> 5;
    const int lane = tid & 31;
    const int wm = wid >> 2;
    const int wn = wid & 3;
    const int lr = lane >> 2;
    const int lc = lane & 3;
    const int r0 = blockIdx.x * BM;

    const int m4    = lane >> 3;
    const int arow  = (lane & 7) + (m4 & 1) * 8;
    const int akoff = (m4 >> 1) * 8;
    const int brow  = lane & 7;
    const int bkoff = ((lane >> 3) & 1) * 8;

    const uint32_t smem_u32 = (uint32_t)__cvta_generic_to_shared(sm);
    const uint32_t AhB0 = smem_u32 + ((wm * 32 + arow) * LDSW + akoff) * 2;
    const uint32_t BhU0 = smem_u32 + 2 * ASTR * 2;
    const uint32_t BhB0 = BhU0 + ((wn * WN + brow) * LDSW + bkoff) * 2;

    float acc[MT][NT][4];
#pragma unroll
    for (int i = 0; i < MT; ++i)
#pragma unroll
        for (int j = 0; j < NT; ++j)
#pragma unroll
            for (int q = 0; q < 4; ++q) acc[i][j][q] = 0.f;

    // ---- W chunk copy into buffer s: BN rows of 128B (8 x 16B) ----
    auto copy_w = [&](int kc, int s) {
        const __half* gw = Wg + (size_t)kc * BN * 64;
        uint32_t base = BhU0 + s * (BSTR * 2);
#pragma unroll
        for (int it = 0; it < (BN * 8) / 256; ++it) {
            int idx = tid + it * 256;
            int row = idx >> 3;
            int j = idx & 7;
            cp_async16(base + row * (LDSW * 2) + j * 16, gw + row * 64 + j * 8);
        }
    };
    // ---- A chunk stage: 64x64 fp32, 4 float4 per thread ----
    float4 aStage[4];
    auto load_stage = [&](int kc) {
#pragma unroll
        for (int it = 0; it < 4; ++it) {
            int idx = tid + it * 256;
            int row = idx >> 4;
            int j4 = (idx & 15) * 4;
            aStage[it] = make_float4(0.f, 0.f, 0.f, 0.f);
            if (r0 + row < M)
                aStage[it] = *(const float4*)(A + (size_t)(r0 + row) * K_TOTAL +
                                              kc * BK + j4);
        }
    };
    // ---- convert staged A chunk into buffer s ----
    auto convert_stage = [&](int s) {
        __half* dst = AhBuf + s * ASTR;
#pragma unroll
        for (int it = 0; it < 4; ++it) {
            int idx = tid + it * 256;
            int row = idx >> 4;
            int j4 = (idx & 15) * 4;
            float4 v = aStage[it];
            int o = row * LDSW + j4;
            *(__half2*)(dst + o)     = __floats2half2_rn(v.x, v.y);
            *(__half2*)(dst + o + 2) = __floats2half2_rn(v.z, v.w);
        }
    };

    // ---- prologue: fill buffer 0 ----
    load_stage(0);
    copy_w(0, 0);
    cp_commit();
    convert_stage(0);
    cp_wait0();
    __syncthreads();

    for (int kc = 0; kc < CHUNKS; ++kc) {
        const int s = kc & 1;
        // issue next-chunk fills before MMA (overlap via scoreboard / async)
        if (kc + 1 < CHUNKS) {
            load_stage(kc + 1);
            copy_w(kc + 1, s ^ 1);
            cp_commit();
        }

        // ---- MMA over buffer s: 4 k16 steps ----
        const uint32_t AhB = AhB0 + s * (ASTR * 2);
        const uint32_t BhB = BhB0 + s * (BSTR * 2);
#pragma unroll
        for (int ks = 0; ks < BK / 16; ++ks) {
            const int k0 = ks * 16;
            uint32_t a[MT][4];
#pragma unroll
            for (int i = 0; i < MT; ++i)
                ldsm_x4(a[i], AhB + (i * 16 * LDSW + k0) * 2);
#pragma unroll
            for (int j = 0; j < NT; ++j) {
                uint32_t b[2];
                ldsm_x2(b, BhB + (j * 8 * LDSW + k0) * 2);
#pragma unroll
                for (int i = 0; i < MT; ++i)
                    mma_fp16(acc[i][j], a[i], b[0], b[1]);
            }
        }

        if (kc + 1 < CHUNKS) {
            convert_stage(s ^ 1);   // writes idle buffer; overlaps other warps' MMA
            cp_wait0();             // next W landed
            __syncthreads();        // single sync per chunk
        }
    }

    // ---- epilogue: bias add + fp16 store ----
#pragma unroll
    for (int j = 0; j < NT; ++j) {
        int col = wn * WN + j * 8 + 2 * lc;
        float bb0 = __ldg(bias + col);
        float bb1 = __ldg(bias + col + 1);
#pragma unroll
        for (int i = 0; i < MT; ++i) {
            int row = r0 + wm * 32 + i * 16 + lr;
            if (row < M)
                *(__half2*)(C + (size_t)row * BN + col) =
                    __floats2half2_rn(acc[i][j][0] + bb0, acc[i][j][1] + bb1);
            if (row + 8 < M)
                *(__half2*)(C + (size_t)(row + 8) * BN + col) =
                    __floats2half2_rn(acc[i][j][2] + bb0, acc[i][j][3] + bb1);
        }
    }
}

// ===========================================================================
// CSR SpMM over fp16 features (identical to R13 structure, fp32 output).
// Thread owns 8 features (one LDG.128 per edge). 8-way edge unroll.
// ===========================================================================
template <int F, bool RELU>
__global__ __launch_bounds__(128) void spmm_fp16_kernel(
    const int* __restrict__ cols, const float* __restrict__ vals,
    const uint4* __restrict__ dense, float* __restrict__ out)
{
    constexpr int F8 = F / 8;
    constexpr int RPB = 128 / F8;
    const int r = blockIdx.x * RPB + threadIdx.x / F8;
    if (r >= N_NODES) return;
    const int f = threadIdx.x % F8;

    int e = g_rp[r];
    const int e_end = g_rp[r + 1];

    float2 a0 = make_float2(0.f, 0.f), a1 = a0, a2 = a0, a3 = a0;

    auto accum = [&](float v, uint4 d) {
        const __half2* ph = (const __half2*)&d;
        float2 x0 = __half22float2(ph[0]);
        float2 x1 = __half22float2(ph[1]);
        float2 x2 = __half22float2(ph[2]);
        float2 x3 = __half22float2(ph[3]);
        a0.x = fmaf(v, x0.x, a0.x); a0.y = fmaf(v, x0.y, a0.y);
        a1.x = fmaf(v, x1.x, a1.x); a1.y = fmaf(v, x1.y, a1.y);
        a2.x = fmaf(v, x2.x, a2.x); a2.y = fmaf(v, x2.y, a2.y);
        a3.x = fmaf(v, x3.x, a3.x); a3.y = fmaf(v, x3.y, a3.y);
    };

    for (; e + 8 <= e_end; e += 8) {
        int   c[8];
        float v[8];
#pragma unroll
        for (int u = 0; u < 8; ++u) c[u] = __ldg(cols + e + u);
#pragma unroll
        for (int u = 0; u < 8; ++u) v[u] = __ldg(vals + e + u);
        uint4 d[8];
#pragma unroll
        for (int u = 0; u < 8; ++u) d[u] = __ldg(dense + (size_t)c[u] * F8 + f);
#pragma unroll
        for (int u = 0; u < 8; ++u) accum(v[u], d[u]);
    }
    for (; e + 4 <= e_end; e += 4) {
        int   c[4];
        float v[4];
#pragma unroll
        for (int u = 0; u < 4; ++u) c[u] = __ldg(cols + e + u);
#pragma unroll
        for (int u = 0; u < 4; ++u) v[u] = __ldg(vals + e + u);
        uint4 d[4];
#pragma unroll
        for (int u = 0; u < 4; ++u) d[u] = __ldg(dense + (size_t)c[u] * F8 + f);
#pragma unroll
        for (int u = 0; u < 4; ++u) accum(v[u], d[u]);
    }
    for (; e < e_end; ++e) {
        int c = __ldg(cols + e);
        float v = __ldg(vals + e);
        accum(v, __ldg(dense + (size_t)c * F8 + f));
    }

    if (RELU) {
        a0.x = fmaxf(a0.x, 0.f); a0.y = fmaxf(a0.y, 0.f);
        a1.x = fmaxf(a1.x, 0.f); a1.y = fmaxf(a1.y, 0.f);
        a2.x = fmaxf(a2.x, 0.f); a2.y = fmaxf(a2.y, 0.f);
        a3.x = fmaxf(a3.x, 0.f); a3.y = fmaxf(a3.y, 0.f);
    }
    float* po = out + (size_t)r * F + f * 8;
    *(float4*)po       = make_float4(a0.x, a0.y, a1.x, a1.y);
    *(float4*)(po + 4) = make_float4(a2.x, a2.y, a3.x, a3.y);
}

// ===========================================================================
// Decode: out[q] = dot(z[src[q]], z[dst[q]]) over OUTF=64. Warp per edge.
// ===========================================================================
__global__ void decode_kernel(const int* __restrict__ ei,
                              const float* __restrict__ z,
                              float* __restrict__ out, int eq)
{
    int q = blockIdx.x * 8 + (threadIdx.x >> 5);
    if (q >= eq) return;
    int lane = threadIdx.x & 31;
    int s = __ldg(ei + q);
    int d = __ldg(ei + eq + q);
    const float* zs = z + (size_t)s * OUTF;
    const float* zd = z + (size_t)d * OUTF;
    float p = zs[lane] * zd[lane] + zs[lane + 32] * zd[lane + 32];
#pragma unroll
    for (int o = 16; o > 0; o >>= 1) p += __shfl_down_sync(0xffffffffu, p, o);
    if (lane == 0) out[q] = p;
}

// ===========================================================================
// Launch
// ===========================================================================
extern "C" void kernel_launch(void* const* d_in, const int* in_sizes, int n_in,
                              void* d_out, int out_size)
{
    const float* x        = (const float*)d_in[0];   // [N, 256]
    const int*   adj_rows = (const int*)  d_in[1];   // [NNZ] sorted
    const int*   adj_cols = (const int*)  d_in[2];   // [NNZ]
    const float* adj_vals = (const float*)d_in[3];   // [NNZ]
    const int*   edge_idx = (const int*)  d_in[4];   // [2, EQ]
    const float* W1       = (const float*)d_in[5];   // [256, 128]
    const float* b1       = (const float*)d_in[6];   // [128]
    const float* W2       = (const float*)d_in[7];   // [128, 64]
    const float* b2       = (const float*)d_in[8];   // [64]
    float* out = (float*)d_out;                      // [EQ]

    const int nnz = in_sizes[1];
    const int eq  = in_sizes[4] / 2;
    const int M   = N_NODES;

    uint4* h0h = nullptr; cudaGetSymbolAddress((void**)&h0h, g_h0h);
    float* h   = nullptr; cudaGetSymbolAddress((void**)&h,   g_h);
    uint4* z0h = nullptr; cudaGetSymbolAddress((void**)&z0h, g_z0h);
    float* z   = nullptr; cudaGetSymbolAddress((void**)&z,   g_z);
    __half* w1 = nullptr; cudaGetSymbolAddress((void**)&w1, g_w1);
    __half* w2 = nullptr; cudaGetSymbolAddress((void**)&w2, g_w2);

    // Dynamic smem: 2 buffers each for A (BM) and W (BN), stride 72 halves
    constexpr int SMEM1 = (2 * 64 + 2 * 128) * 72 * 2;  // 55296 (BN=128)
    constexpr int SMEM2 = (2 * 64 + 2 * 64) * 72 * 2;   // 36864 (BN=64)
    cudaFuncSetAttribute(mma_gemm_fp16<IN_F, HID>,
                         cudaFuncAttributeMaxDynamicSharedMemorySize, SMEM1);
    cudaFuncSetAttribute(mma_gemm_fp16<HID, OUTF>,
                         cudaFuncAttributeMaxDynamicSharedMemorySize, SMEM2);

    const int gblocks = (M + 63) / 64;   // 1563

    // 0. pre-convert weights (fp16, chunk-major transposed)
    conv_w_kernel<<<(IN_F * HID + 255) / 256, 256>>>(W1, w1, IN_F, HID);
    conv_w_kernel<<<(HID * OUTF + 255) / 256, 256>>>(W2, w2, HID, OUTF);

    // 1. row pointers from sorted rows
    build_rowptr_kernel<<<(nnz + 255) / 256, 256>>>(adj_rows, nnz);

    // 2. h0 = x @ W1 + b1   (fp16 single-pass, double-buffered)
    mma_gemm_fp16<IN_F, HID><<<gblocks, 256, SMEM1>>>(
        x, w1, b1, (__half*)h0h, M);

    // 3. h = relu(spmm(h0)) -> fp32 (R13 structure)
    spmm_fp16_kernel<HID, true><<<(M + 7) / 8, 128>>>(
        adj_cols, adj_vals, h0h, h);

    // 4. z0 = h @ W2 + b2   (fp16 single-pass, double-buffered)
    mma_gemm_fp16<HID, OUTF><<<gblocks, 256, SMEM2>>>(
        h, w2, b2, (__half*)z0h, M);

    // 5. z = spmm(z0) -> fp32
    spmm_fp16_kernel<OUTF, false><<<(M + 15) / 16, 128>>>(
        adj_cols, adj_vals, z0h, z);

    // 6. edge dot products
    decode_kernel<<<(eq + 7) / 8, 256>>>(edge_idx, z, out, eq);
}